// round 3
// baseline (speedup 1.0000x reference)
#include <cuda_runtime.h>
#include <cstdint>

// ---------------------------------------------------------------------------
// MoE_72808285602017 — PropertyLossTracker fused segment reduction
//   inputs : property_ids (N int32), token_losses (N f32),
//            prop_freq (P f32), batch_counter (1 int32)
//   outputs: [stratified_loss, unweighted_loss, new_freq[P]]  (P+2 f32)
//
// R3: single fused kernel. Per-block shared 32-bit packed atomics, global
//     64-bit packed flush, fence+ticket "last block" epilogue (no 2nd launch).
// ---------------------------------------------------------------------------

#define NPROP 4096
#define NBLOCKS 296

// Local 32-bit cell: (count << 24) + round(loss * 2^16), built as one FFMA+F2I:
//   __float2uint_rn(loss * 65536.0f + 16777216.0f)
#define LSCALE 65536.0f
#define LBIAS  16777216.0f           // 2^24 == one count unit
#define LCNT_SHIFT 24

// Global 64-bit cell: (count << 40) + sum_units16
#define GCNT_SHIFT 40
#define GINV_SCALE (1.0f / 65536.0f)

__device__ unsigned long long g_acc[NPROP];   // zero at load; last block re-zeroes
__device__ unsigned int       g_ticket;       // zero at load; last block re-zeroes

__global__ void __launch_bounds__(1024, 2)
fused_kernel(const int* __restrict__ ids,
             const float* __restrict__ losses,
             const float* __restrict__ prop_freq,
             const int* __restrict__ bc_ptr,
             float* __restrict__ out,
             long long n)
{
    __shared__ unsigned int s_acc[NPROP];
    __shared__ bool s_last;
    #pragma unroll
    for (int i = threadIdx.x; i < NPROP; i += 1024) s_acc[i] = 0u;
    __syncthreads();

    // ---- phase 1: token accumulation into shared -----------------------
    const long long n4 = n >> 2;                 // N is a multiple of 4
    const int4*   id4 = (const int4*)ids;
    const float4* ls4 = (const float4*)losses;
    const long long stride = (long long)gridDim.x * 1024;

    long long i = (long long)blockIdx.x * 1024 + threadIdx.x;
    #pragma unroll 4
    for (; i < n4; i += stride) {
        int4   id = id4[i];
        float4 ls = ls4[i];
        atomicAdd(&s_acc[id.x], __float2uint_rn(fmaf(ls.x, LSCALE, LBIAS)));
        atomicAdd(&s_acc[id.y], __float2uint_rn(fmaf(ls.y, LSCALE, LBIAS)));
        atomicAdd(&s_acc[id.z], __float2uint_rn(fmaf(ls.z, LSCALE, LBIAS)));
        atomicAdd(&s_acc[id.w], __float2uint_rn(fmaf(ls.w, LSCALE, LBIAS)));
    }
    // scalar tail (defensive; N % 4 == 0 here)
    for (long long t = (n4 << 2) + (long long)blockIdx.x * 1024 + threadIdx.x;
         t < n; t += stride) {
        atomicAdd(&s_acc[ids[t]], __float2uint_rn(fmaf(losses[t], LSCALE, LBIAS)));
    }
    __syncthreads();

    // ---- phase 2: flush block partials to global (64-bit packed) -------
    #pragma unroll
    for (int k = threadIdx.x; k < NPROP; k += 1024) {
        unsigned int v = s_acc[k];
        if (v) {
            unsigned long long g =
                ((unsigned long long)(v >> LCNT_SHIFT) << GCNT_SHIFT)
                + (unsigned long long)(v & 0x00FFFFFFu);
            atomicAdd(&g_acc[k], g);
        }
    }

    // ---- phase 3: fence + ticket; last block runs the epilogue ---------
    __threadfence();
    if (threadIdx.x == 0)
        s_last = (atomicAdd(&g_ticket, 1u) == (unsigned)(gridDim.x - 1));
    __syncthreads();
    if (!s_last) return;
    __threadfence();   // acquire: all blocks' g_acc atomics visible

    const int tid = threadIdx.x;
    const float bc = (float)bc_ptr[0];
    const float n_tokens = (float)n;

    const float EMA_DECAY = 0.99f;
    const float ONE_MINUS = 1.0f - 0.99f;
    const float MIN_FREQ  = 1e-5f;
    const float MAX_W     = 30.0f;
    const float WARMUP    = 1000.0f;
    const float SLOW      = 3000.0f;
    const float RAMPB     = 200.0f;

    float s_mw = 0.0f, s_w = 0.0f, s_t = 0.0f;

    #pragma unroll
    for (int k = tid; k < NPROP; k += 1024) {
        unsigned long long v = __ldcg(&g_acc[k]);   // L2-coherent with atomics
        g_acc[k] = 0ULL;                            // reset for next replay
        float cnt = (float)(v >> GCNT_SHIFT);
        float sum = (float)(v & ((1ULL << GCNT_SHIFT) - 1ULL)) * GINV_SCALE;
        bool present = cnt > 0.0f;

        float mean = present ? (sum / fmaxf(cnt, 1.0f)) : 0.0f;

        // EMA frequency update
        float bfreq = cnt / (n_tokens + 1e-6f);
        float nf = prop_freq[k] * EMA_DECAY + (present ? ONE_MINUS * bfreq : 0.0f);
        out[2 + k] = nf;

        // inverse-frequency weight with warmup/ramp branches
        float fc  = fmaxf(nf, MIN_FREQ);
        float raw = rsqrtf(fc + 1e-6f);             // 1/f^0.5
        float ramp = fminf(1.0f, (bc - WARMUP) / RAMPB);
        raw = 1.0f + ramp * (raw - 1.0f);
        raw = fminf(MAX_W, raw);
        float frac = bc / SLOW;
        if (bc <= SLOW)   raw = raw * frac + (1.0f - frac);
        if (bc <= WARMUP) raw = 1.0f;

        float w = present ? raw : 0.0f;
        s_w  += w;
        s_mw += mean * w;
        s_t  += sum;
    }

    // block tree reduction of (s_mw, s_w, s_t); reuse s_acc as scratch
    float* r_mw = (float*)&s_acc[0];
    float* r_w  = (float*)&s_acc[32];
    float* r_t  = (float*)&s_acc[64];
    const unsigned FULL = 0xFFFFFFFFu;
    #pragma unroll
    for (int off = 16; off > 0; off >>= 1) {
        s_mw += __shfl_down_sync(FULL, s_mw, off);
        s_w  += __shfl_down_sync(FULL, s_w,  off);
        s_t  += __shfl_down_sync(FULL, s_t,  off);
    }
    int lane = tid & 31, warp = tid >> 5;
    if (lane == 0) { r_mw[warp] = s_mw; r_w[warp] = s_w; r_t[warp] = s_t; }
    __syncthreads();
    if (warp == 0) {
        s_mw = r_mw[lane]; s_w = r_w[lane]; s_t = r_t[lane];
        #pragma unroll
        for (int off = 16; off > 0; off >>= 1) {
            s_mw += __shfl_down_sync(FULL, s_mw, off);
            s_w  += __shfl_down_sync(FULL, s_w,  off);
            s_t  += __shfl_down_sync(FULL, s_t,  off);
        }
        if (lane == 0) {
            out[0] = s_mw / (s_w + 1e-6f);   // stratified loss
            out[1] = s_t / n_tokens;         // unweighted mean loss
            g_ticket = 0;                    // reset for next replay
        }
    }
}

// ---------------------------------------------------------------------------
extern "C" void kernel_launch(void* const* d_in, const int* in_sizes, int n_in,
                              void* d_out, int out_size)
{
    const int*   ids    = (const int*)d_in[0];
    const float* losses = (const float*)d_in[1];
    const float* freq   = (const float*)d_in[2];
    const int*   bc     = (const int*)d_in[3];
    long long n = (long long)in_sizes[0];
    float* out = (float*)d_out;

    fused_kernel<<<NBLOCKS, 1024>>>(ids, losses, freq, bc, out, n);
}